// round 6
// baseline (speedup 1.0000x reference)
#include <cuda_runtime.h>
#include <cstdint>

#define BATCH 64
#define SEQ 50
#define GN 50
#define KNB 12
#define DIM 256
#define GP1 51          // G + 1 (pad row)
#define ROWS_N (BATCH*GP1)      // 3264 node rows
#define ROWS_PAD 3328           // padded to 26*128 for BM=128 GEMMs
#define NEGF (-9e15f)

// ---------------- device scratch (static allocation, allowed) ----------------
__device__ int   g_ifn[BATCH*GN];
__device__ int   g_canon[BATCH*GN];
__device__ int   g_src0[BATCH*SEQ];
__device__ int   g_tknode[BATCH*GN*KNB];
__device__ float g_softw[BATCH*GN*KNB];
__device__ __align__(16) float g_CX[ROWS_PAD*512];
__device__ __align__(16) float g_Xn[ROWS_PAD*256];
__device__ __align__(16) float g_CH[ROWS_PAD*512];
__device__ __align__(16) float g_Hn[ROWS_PAD*256];
__device__ __align__(16) float g_Hs[ROWS_PAD*256];
__device__ __align__(16) float g_P [64*256];
__device__ __align__(16) float g_ph[BATCH*SEQ*256];
__device__ __align__(16) float g_h [BATCH*SEQ*256];
__device__ __align__(16) float g_v [BATCH*256];
__device__ __align__(16) float g_z [BATCH*SEQ*256];
__device__ __align__(16) float g_sl[BATCH*256];
__device__ __align__(16) float g_sb[BATCH*SEQ*256];
__device__ __align__(16) float g_vg[BATCH*256];
__device__ __align__(16) float g_zg[BATCH*SEQ*256];
__device__ __align__(16) float g_CO[BATCH*512];

// ---------------- setup: inv perm, item_for_node, canon, src0, topk+softmax --
__global__ void setup_kernel(const int* __restrict__ data,
                             const float* __restrict__ adj,
                             const int* __restrict__ alias,
                             const int* __restrict__ cur)
{
    int b = blockIdx.x, tid = threadIdx.x;            // 64 threads
    __shared__ float adjS[GN*GN];
    __shared__ int curS[GN], aliasS[GN], invS[GN], ifnS[GN];

    for (int i = tid; i < GN; i += 64) { curS[i] = cur[b*GN+i]; aliasS[i] = alias[b*GN+i]; }
    __syncthreads();
    for (int i = tid; i < GN; i += 64) invS[aliasS[i]] = i;
    __syncthreads();
    for (int i = tid; i < GN; i += 64) { int t = curS[invS[i]]; ifnS[i] = t; g_ifn[b*GN+i] = t; }
    __syncthreads();
    // canonical node of each node's item (first position in cur, argmax semantics)
    for (int j = tid; j < GN; j += 64) {
        int t = ifnS[j];
        int c = aliasS[0];
        for (int p = 0; p < GN; p++) if (curS[p] == t) { c = aliasS[p]; break; }
        g_canon[b*GN+j] = c;
    }
    // canonical node of each data position (-1 for pad)
    for (int s = tid; s < SEQ; s += 64) {
        int t = data[b*SEQ+s];
        int r = -1;
        if (t != 0) {
            r = aliasS[0];
            for (int p = 0; p < GN; p++) if (curS[p] == t) { r = aliasS[p]; break; }
        }
        g_src0[b*SEQ+s] = r;
    }
    // stage adjacency, transform 0 -> NEG
    for (int i = tid; i < GN*GN; i += 64) {
        float v = adj[(size_t)b*GN*GN + i];
        adjS[i] = (v > 0.f) ? v : NEGF;
    }
    __syncthreads();
    // top-K per node row (descending, first-index tie break) + softmax weights
    if (tid < GN) {
        int j = tid;
        float* row = &adjS[j*GN];
        float nw[KNB]; int nd[KNB];
        for (int k = 0; k < KNB; k++) {
            float best = row[0]; int bi = 0;
            for (int i = 1; i < GN; i++) { float v = row[i]; if (v > best) { best = v; bi = i; } }
            row[bi] = -3.0e38f;
            bool valid = best > (NEGF * 0.5f);
            nd[k] = valid ? bi : -1;
            nw[k] = valid ? best : NEGF;
        }
        float m = nw[0];
        for (int k = 1; k < KNB; k++) m = fmaxf(m, nw[k]);
        float p[KNB], sum = 0.f;
        for (int k = 0; k < KNB; k++) { p[k] = expf(nw[k]-m); sum += p[k]; }
        float inv = 1.f / sum;
        for (int k = 0; k < KNB; k++) {
            g_softw [(b*GN+j)*KNB+k] = p[k]*inv;
            g_tknode[(b*GN+j)*KNB+k] = nd[k];
        }
    }
}

// ---------------- CX = [E(node), aggE(node)] per (b, node) + pad row ---------
// 256 threads, 4 node-rows per block
__global__ void cx_kernel(const float* __restrict__ emb)
{
    int tid = threadIdx.x;
    int row = blockIdx.x*4 + (tid>>6);
    int c = tid & 63;
    if (row >= ROWS_N) return;
    int b = row / GP1, j = row - b*GP1;
    float4* dst = (float4*)&g_CX[(size_t)row*512];
    if (j == GN) {
        float4 v = ((const float4*)emb)[c];           // embedding[0]
        dst[c] = v; dst[64+c] = v;
        return;
    }
    int item = g_ifn[b*GN+j];
    dst[c] = ((const float4*)(emb + (size_t)item*DIM))[c];
    float4 acc = {0.f,0.f,0.f,0.f};
    #pragma unroll
    for (int k = 0; k < KNB; k++) {
        float sw = g_softw[(b*GN+j)*KNB+k];
        int nd = g_tknode[(b*GN+j)*KNB+k];
        int it2 = (nd >= 0) ? g_ifn[b*GN+nd] : 0;
        float4 vv = ((const float4*)(emb + (size_t)it2*DIM))[c];
        acc.x += sw*vv.x; acc.y += sw*vv.y; acc.z += sw*vv.z; acc.w += sw*vv.w;
    }
    dst[64+c] = acc;
}

// ---------------- CH = [X(node), AGG2(node)] ---------------------------------
__global__ void ch_kernel()
{
    int tid = threadIdx.x;
    int row = blockIdx.x*4 + (tid>>6);
    int c = tid & 63;
    if (row >= ROWS_N) return;
    int b = row / GP1, j = row - b*GP1;
    float4* dst = (float4*)&g_CH[(size_t)row*512];
    const float4* xb = (const float4*)(g_Xn + (size_t)b*GP1*DIM);
    if (j == GN) {
        float4 v = xb[GN*64 + c];                     // X_pad
        dst[c] = v; dst[64+c] = v;
        return;
    }
    dst[c] = xb[j*64 + c];
    float4 acc = {0.f,0.f,0.f,0.f};
    #pragma unroll
    for (int k = 0; k < KNB; k++) {
        float sw = g_softw[(b*GN+j)*KNB+k];
        int nd = g_tknode[(b*GN+j)*KNB+k];
        int jj = (nd >= 0) ? g_canon[b*GN+nd] : GN;   // invalid -> pad row
        float4 vv = xb[jj*64 + c];
        acc.x += sw*vv.x; acc.y += sw*vv.y; acc.z += sw*vv.z; acc.w += sw*vv.w;
    }
    dst[64+c] = acc;
}

// ---------------- sb = lrelu(P[s] + Hs[b, src0|pad])  (replaces CS + big GEMM)
__global__ void sbg_kernel()
{
    int tid = threadIdx.x;
    int idx = blockIdx.x*4 + (tid>>6);                // 0..3199
    int c = tid & 63;
    int b = idx / SEQ, s = idx - b*SEQ;
    float4 p = ((const float4*)g_P)[s*64 + c];
    int src = g_src0[idx];
    int jj = (src >= 0) ? src : GN;
    float4 hv = ((const float4*)g_Hs)[(size_t)(b*GP1+jj)*64 + c];
    float4 o;
    o.x = p.x + hv.x; o.y = p.y + hv.y; o.z = p.z + hv.z; o.w = p.w + hv.w;
    o.x = o.x > 0.f ? o.x : 0.2f*o.x;
    o.y = o.y > 0.f ? o.y : 0.2f*o.y;
    o.z = o.z > 0.f ? o.z : 0.2f*o.z;
    o.w = o.w > 0.f ? o.w : 0.2f*o.w;
    ((float4*)g_sb)[(size_t)idx*64 + c] = o;
}

// ---------------- ph = path @ hidden (hidden = embedding[data]) --------------
__global__ void ph_kernel(const float* __restrict__ path,
                          const float* __restrict__ emb,
                          const int* __restrict__ data)
{
    int b = blockIdx.x;
    int n0 = blockIdx.y * 64;
    int tid = threadIdx.x;                             // 256 threads
    __shared__ float pS[SEQ*SEQ];
    __shared__ const float* rp[SEQ];
    for (int i = tid; i < SEQ*SEQ; i += 256) pS[i] = path[(size_t)b*SEQ*SEQ + i];
    if (tid < SEQ) rp[tid] = emb + (size_t)data[b*SEQ+tid]*DIM;
    __syncthreads();
    int c = tid & 63;
    int sg = tid >> 6;                                 // 0..3
    int ns = (sg < 2) ? 13 : 12;
    float acc[13];
    #pragma unroll
    for (int i = 0; i < 13; i++) acc[i] = 0.f;
    for (int t = 0; t < SEQ; t++) {
        float hv = rp[t][n0 + c];
        #pragma unroll
        for (int ss = 0; ss < 13; ss++) {
            if (ss < ns) {
                int s = sg + 4*ss;
                acc[ss] += pS[s*SEQ + t] * hv;
            }
        }
    }
    for (int ss = 0; ss < ns; ss++) {
        int s = sg + 4*ss;
        g_ph[((size_t)(b*SEQ+s))*DIM + n0 + c] = acc[ss];
    }
}

// ---------------- BM=64 GEMM (small M) ---------------------------------------
__global__ void gemm64(const float* __restrict__ A, const float* __restrict__ W,
                       float* __restrict__ C, int M, int K,
                       const float* __restrict__ bias,
                       const float* __restrict__ rowadd, int rows_per_b,
                       int do_lrelu)
{
    __shared__ __align__(16) float As[16][68];
    __shared__ __align__(16) float Ws[16][64];
    int m0 = blockIdx.x * 64;
    int n0 = blockIdx.y * 64;
    int tid = threadIdx.x;
    int tr = tid >> 4, tc = tid & 15;
    int arow = tid >> 2, acol = (tid & 3) * 4;
    int wrow = tid >> 4, wcol = (tid & 15) * 4;
    float acc[4][4] = {};
    for (int k0 = 0; k0 < K; k0 += 16) {
        float4 av = *(const float4*)&A[(size_t)(m0+arow)*K + k0 + acol];
        As[acol+0][arow] = av.x; As[acol+1][arow] = av.y;
        As[acol+2][arow] = av.z; As[acol+3][arow] = av.w;
        *(float4*)&Ws[wrow][wcol] = *(const float4*)&W[(size_t)(k0+wrow)*256 + n0 + wcol];
        __syncthreads();
        #pragma unroll
        for (int k = 0; k < 16; k++) {
            float4 a = *(const float4*)&As[k][tr*4];
            float4 w = *(const float4*)&Ws[k][tc*4];
            float ar[4] = {a.x,a.y,a.z,a.w};
            float wr[4] = {w.x,w.y,w.z,w.w};
            #pragma unroll
            for (int i = 0; i < 4; i++)
                #pragma unroll
                for (int j = 0; j < 4; j++) acc[i][j] += ar[i]*wr[j];
        }
        __syncthreads();
    }
    #pragma unroll
    for (int i = 0; i < 4; i++) {
        int r = m0 + tr*4 + i;
        int cb = n0 + tc*4;
        float4 o; float* op = &o.x;
        #pragma unroll
        for (int j = 0; j < 4; j++) {
            float v = acc[i][j];
            if (bias)   v += bias[cb+j];
            if (rowadd) v += rowadd[(r/rows_per_b)*256 + cb + j];
            if (do_lrelu) v = (v > 0.f) ? v : 0.2f*v;
            op[j] = v;
        }
        *(float4*)&C[(size_t)r*256 + cb] = o;
    }
}

// ---------------- BM=128 GEMM (large M, rows padded to multiple of 128) ------
__global__ void gemm128(const float* __restrict__ A, const float* __restrict__ W,
                        float* __restrict__ C, int K,
                        const float* __restrict__ bias,
                        const float* __restrict__ rowadd,
                        int do_lrelu)
{
    __shared__ __align__(16) float As[16][132];
    __shared__ __align__(16) float Ws[16][64];
    int m0 = blockIdx.x * 128;
    int n0 = blockIdx.y * 64;
    int tid = threadIdx.x;
    int tr = tid >> 4, tc = tid & 15;                  // 8-row x 4-col micro-tile
    int wrow = tid >> 4, wcol = (tid & 15) * 4;
    float acc[8][4] = {};
    for (int k0 = 0; k0 < K; k0 += 16) {
        #pragma unroll
        for (int t = 0; t < 2; t++) {
            int idx = tid*2 + t;
            int row = idx >> 2, cg = (idx & 3) * 4;
            float4 av = *(const float4*)&A[(size_t)(m0+row)*K + k0 + cg];
            As[cg+0][row]=av.x; As[cg+1][row]=av.y; As[cg+2][row]=av.z; As[cg+3][row]=av.w;
        }
        *(float4*)&Ws[wrow][wcol] = *(const float4*)&W[(size_t)(k0+wrow)*256 + n0 + wcol];
        __syncthreads();
        #pragma unroll
        for (int k = 0; k < 16; k++) {
            float4 a0 = *(const float4*)&As[k][tr*8];
            float4 a1 = *(const float4*)&As[k][tr*8+4];
            float4 w  = *(const float4*)&Ws[k][tc*4];
            float ar[8]={a0.x,a0.y,a0.z,a0.w,a1.x,a1.y,a1.z,a1.w};
            float wr[4]={w.x,w.y,w.z,w.w};
            #pragma unroll
            for (int i=0;i<8;i++)
                #pragma unroll
                for (int j=0;j<4;j++) acc[i][j]+=ar[i]*wr[j];
        }
        __syncthreads();
    }
    #pragma unroll
    for (int i = 0; i < 8; i++) {
        int r = m0 + tr*8 + i;
        int cb = n0 + tc*4;
        float4 o; float* op = &o.x;
        #pragma unroll
        for (int j = 0; j < 4; j++) {
            float v = acc[i][j];
            if (bias)   v += bias[cb+j];
            if (rowadd) v += rowadd[(r/SEQ)*256 + cb + j];
            if (do_lrelu) v = (v > 0.f) ? v : 0.2f*v;
            op[j] = v;
        }
        *(float4*)&C[(size_t)r*256 + cb] = o;
    }
}

// ---------------- fused: last = sum(mask)-1 ; v = h[b,last]@w_2 + b_l --------
__global__ void htv_kernel(const float* __restrict__ mask,
                           const float* __restrict__ w2,
                           const float* __restrict__ bl)
{
    int b = blockIdx.x, tid = threadIdx.x;             // 256 threads
    __shared__ float hS[256];
    __shared__ int lastS;
    if (tid == 0) {
        float s = 0.f;
        for (int i = 0; i < SEQ; i++) s += mask[b*SEQ+i];
        lastS = (int)(s - 1.0f);
    }
    __syncthreads();
    hS[tid] = g_h[((size_t)(b*SEQ+lastS))*DIM + tid];
    __syncthreads();
    float acc = bl[tid];
    for (int k = 0; k < 256; k++) acc += hS[k]*w2[k*256 + tid];
    g_v[b*256 + tid] = acc;
}

// ---------------- vec-mat: y[b] = (x[b] @ Wm) (+bias) (lrelu?) ---------------
__global__ void vecmat(const float* __restrict__ x, int xstride,
                       const float* __restrict__ Wm, int K,
                       const float* __restrict__ bias,
                       float* __restrict__ y, int do_lrelu)
{
    int b = blockIdx.x, tid = threadIdx.x;             // 256 threads
    __shared__ float xS[512];
    for (int i = tid; i < K; i += 256) xS[i] = x[(size_t)b*xstride + i];
    __syncthreads();
    float acc = bias ? bias[tid] : 0.f;
    for (int k = 0; k < K; k++) acc += xS[k]*Wm[(size_t)k*256 + tid];
    if (do_lrelu) acc = (acc > 0.f) ? acc : 0.2f*acc;
    y[b*256 + tid] = acc;
}

// ---------------- softmax pooling: e=z.q ; softmax ; out = sum p*h -----------
__global__ void pool_kernel(const float* __restrict__ z, const float* __restrict__ qv,
                            const float* __restrict__ hsrc,
                            const float* __restrict__ mask,   // nullable
                            float* __restrict__ outv,         // used if CO==null
                            const float* __restrict__ slin,   // used if CO!=null
                            float* __restrict__ CO)           // nullable
{
    int b = blockIdx.x, tid = threadIdx.x;
    int lane = tid & 31, wp = tid >> 5;
    __shared__ float eS[SEQ], pS[SEQ];
    for (int s = wp; s < SEQ; s += 8) {
        const float* zr = z + ((size_t)(b*SEQ+s))*DIM;
        float d = 0.f;
        for (int i = lane; i < DIM; i += 32) d += zr[i]*qv[i];
        for (int o = 16; o; o >>= 1) d += __shfl_xor_sync(0xffffffffu, d, o);
        if (!lane) eS[s] = d;
    }
    __syncthreads();
    if (tid == 0) {
        float m = -3.4e38f;
        for (int s = 0; s < SEQ; s++) {
            float e = eS[s];
            if (mask && !(mask[b*SEQ+s] > 0.f)) e = NEGF;
            eS[s] = e; m = fmaxf(m, e);
        }
        float sum = 0.f;
        for (int s = 0; s < SEQ; s++) { float p = expf(eS[s]-m); pS[s] = p; sum += p; }
        float inv = 1.f / sum;
        for (int s = 0; s < SEQ; s++) pS[s] *= inv;
    }
    __syncthreads();
    float acc = 0.f;
    for (int s = 0; s < SEQ; s++) acc += pS[s] * hsrc[((size_t)(b*SEQ+s))*DIM + tid];
    if (CO) {
        CO[b*512 + tid]       = slin[b*256 + tid];
        CO[b*512 + 256 + tid] = acc;
    } else {
        outv[b*256 + tid] = acc;
    }
}

// ---------------- launch ----------------------------------------------------
extern "C" void kernel_launch(void* const* d_in, const int* in_sizes, int n_in,
                              void* d_out, int out_size)
{
    const int*   data  = (const int*)  d_in[0];
    const float* mask  = (const float*)d_in[1];
    const float* adj   = (const float*)d_in[2];
    const int*   alias = (const int*)  d_in[3];
    const int*   cur   = (const int*)  d_in[4];
    const float* path  = (const float*)d_in[5];
    const float* emb   = (const float*)d_in[6];
    const float* pos   = (const float*)d_in[7];
    const float* w3    = (const float*)d_in[8];
    const float* b1    = (const float*)d_in[9];
    const float* q     = (const float*)d_in[10];
    const float* wg1   = (const float*)d_in[11];
    const float* wg2   = (const float*)d_in[12];
    const float* b2    = (const float*)d_in[13];
    const float* wh    = (const float*)d_in[14];
    const float* wp    = (const float*)d_in[15];
    const float* w1    = (const float*)d_in[16];
    const float* w2    = (const float*)d_in[17];
    const float* bl    = (const float*)d_in[18];
    const float* ql    = (const float*)d_in[19];
    const float* wagg  = (const float*)d_in[20];   // [2,512,256]
    const float* bagg  = (const float*)d_in[21];   // [2,256]
    float* out = (float*)d_out;

    float *CX,*Xn,*CH,*Hn,*Hs,*P,*ph,*h,*v,*z,*sl,*sb,*vg,*zg,*CO;
    cudaGetSymbolAddress((void**)&CX, g_CX);
    cudaGetSymbolAddress((void**)&Xn, g_Xn);
    cudaGetSymbolAddress((void**)&CH, g_CH);
    cudaGetSymbolAddress((void**)&Hn, g_Hn);
    cudaGetSymbolAddress((void**)&Hs, g_Hs);
    cudaGetSymbolAddress((void**)&P,  g_P);
    cudaGetSymbolAddress((void**)&ph, g_ph);
    cudaGetSymbolAddress((void**)&h,  g_h);
    cudaGetSymbolAddress((void**)&v,  g_v);
    cudaGetSymbolAddress((void**)&z,  g_z);
    cudaGetSymbolAddress((void**)&sl, g_sl);
    cudaGetSymbolAddress((void**)&sb, g_sb);
    cudaGetSymbolAddress((void**)&vg, g_vg);
    cudaGetSymbolAddress((void**)&zg, g_zg);
    cudaGetSymbolAddress((void**)&CO, g_CO);

    // Side stream + fork/join events (created once, outside any capture; every
    // call performs the identical launch sequence).
    static cudaStream_t sB = nullptr;
    static cudaEvent_t evF = nullptr, evJ = nullptr;
    if (!sB) {
        cudaStreamCreateWithFlags(&sB, cudaStreamNonBlocking);
        cudaEventCreateWithFlags(&evF, cudaEventDisableTiming);
        cudaEventCreateWithFlags(&evJ, cudaEventDisableTiming);
    }

    // ---- fork: local-intent chain runs on sB concurrently with global chain ----
    cudaEventRecord(evF, 0);
    cudaStreamWaitEvent(sB, evF, 0);

    // ==== stream 0: GlobalIntent chain ====
    setup_kernel<<<BATCH, 64>>>(data, adj, alias, cur);
    cx_kernel<<<(ROWS_N+3)/4, 256>>>(emb);
    // X = lrelu(CX @ w_agg0 + b_agg0)   [3328,512]x[512,256]
    gemm128<<<dim3(ROWS_PAD/128,4), 256>>>(CX, wagg, Xn, 512, bagg, nullptr, 1);
    ch_kernel<<<(ROWS_N+3)/4, 256>>>();
    // H = lrelu(CH @ w_agg1 + b_agg1)
    gemm128<<<dim3(ROWS_PAD/128,4), 256>>>(CH, wagg + 512*256, Hn, 512, bagg + 256, nullptr, 1);
    // Hs = Hn @ w3_bottom   (h_global half of the fusion GEMM, per node row)
    gemm128<<<dim3(ROWS_PAD/128,4), 256>>>(Hn, w3 + 256*256, Hs, 256, nullptr, nullptr, 0);

    // ==== stream sB: LocalIntent chain (independent of global chain) ====
    // P = pos[:64] @ w3_top + b1   (batch-independent half of fusion GEMM)
    gemm64<<<dim3(1,4), 256, 0, sB>>>(pos, w3, P, 64, 256, b1, nullptr, 1, 0);
    ph_kernel<<<dim3(BATCH,4), 256, 0, sB>>>(path, emb, data);
    gemm128<<<dim3(25,4), 256, 0, sB>>>(ph, wp, h, 256, nullptr, nullptr, 1);   // h = lrelu(ph@w_p)
    htv_kernel<<<BATCH, 256, 0, sB>>>(mask, w2, bl);                            // v = h[last]@w_2+b_l
    gemm128<<<dim3(25,4), 256, 0, sB>>>(h, w1, z, 256, nullptr, v, 1);          // z = lrelu(h@w_1+v[b])
    pool_kernel<<<BATCH, 256, 0, sB>>>(z, ql, h, mask, sl, nullptr, nullptr);   // s_l
    vecmat<<<BATCH, 256, 0, sB>>>(sl, 256, wg2, 256, b2, vg, 0);                // vg = s_l@w_g2+b_2
    cudaEventRecord(evJ, sB);

    // ---- join ----
    cudaStreamWaitEvent(0, evJ, 0);

    // ==== stream 0: fusion tail ====
    sbg_kernel<<<BATCH*SEQ/4, 256>>>();                                         // s = lrelu(P+Hs+b1)
    gemm128<<<dim3(25,4), 256>>>(sb, wg1, zg, 256, nullptr, vg, 1);             // zg
    pool_kernel<<<BATCH, 256>>>(zg, q, sb, nullptr, nullptr, sl, CO);           // s_g, CO=[s_l,s_g]
    vecmat<<<BATCH, 256>>>(CO, 512, wh, 512, nullptr, out, 1);                  // out = lrelu(CO@w_h)
}

// round 7
// speedup vs baseline: 1.0070x; 1.0070x over previous
#include <cuda_runtime.h>
#include <cstdint>

#define BATCH 64
#define SEQ 50
#define GN 50
#define KNB 12
#define DIM 256
#define GP1 51          // G + 1 (pad row)
#define ROWS_N (BATCH*GP1)      // 3264 node rows
#define ROWS_PAD 3328           // padded to 26*128 for BM=128 GEMMs
#define NEGF (-9e15f)

// ---------------- device scratch (static allocation, allowed) ----------------
__device__ int   g_ifn[BATCH*GN];
__device__ int   g_canon[BATCH*GN];
__device__ int   g_src0[BATCH*SEQ];
__device__ int   g_tknode[BATCH*GN*KNB];
__device__ float g_softw[BATCH*GN*KNB];
__device__ __align__(16) float g_CX[ROWS_PAD*512];
__device__ __align__(16) float g_Xn[ROWS_PAD*256];
__device__ __align__(16) float g_CH[ROWS_PAD*512];
__device__ __align__(16) float g_Hn[ROWS_PAD*256];
__device__ __align__(16) float g_Hs[ROWS_PAD*256];
__device__ __align__(16) float g_P [64*256];
__device__ __align__(16) float g_ph[BATCH*SEQ*256];
__device__ __align__(16) float g_h [BATCH*SEQ*256];
__device__ __align__(16) float g_v [BATCH*256];
__device__ __align__(16) float g_z [BATCH*SEQ*256];
__device__ __align__(16) float g_sl[BATCH*256];
__device__ __align__(16) float g_sb[BATCH*SEQ*256];
__device__ __align__(16) float g_vg[BATCH*256];
__device__ __align__(16) float g_zg[BATCH*SEQ*256];
__device__ __align__(16) float g_CO[BATCH*512];

// ---------------- setup: inv perm, item_for_node, canon, src0, topk+softmax --
__global__ void setup_kernel(const int* __restrict__ data,
                             const float* __restrict__ adj,
                             const int* __restrict__ alias,
                             const int* __restrict__ cur)
{
    int b = blockIdx.x, tid = threadIdx.x;            // 64 threads
    __shared__ float adjS[GN*GN];
    __shared__ int curS[GN], aliasS[GN], invS[GN], ifnS[GN];

    for (int i = tid; i < GN; i += 64) { curS[i] = cur[b*GN+i]; aliasS[i] = alias[b*GN+i]; }
    __syncthreads();
    for (int i = tid; i < GN; i += 64) invS[aliasS[i]] = i;
    __syncthreads();
    for (int i = tid; i < GN; i += 64) { int t = curS[invS[i]]; ifnS[i] = t; g_ifn[b*GN+i] = t; }
    __syncthreads();
    // canonical node of each node's item (first position in cur, argmax semantics)
    for (int j = tid; j < GN; j += 64) {
        int t = ifnS[j];
        int c = aliasS[0];
        for (int p = 0; p < GN; p++) if (curS[p] == t) { c = aliasS[p]; break; }
        g_canon[b*GN+j] = c;
    }
    // canonical node of each data position (-1 for pad)
    for (int s = tid; s < SEQ; s += 64) {
        int t = data[b*SEQ+s];
        int r = -1;
        if (t != 0) {
            r = aliasS[0];
            for (int p = 0; p < GN; p++) if (curS[p] == t) { r = aliasS[p]; break; }
        }
        g_src0[b*SEQ+s] = r;
    }
    // stage adjacency, transform 0 -> NEG
    for (int i = tid; i < GN*GN; i += 64) {
        float v = adj[(size_t)b*GN*GN + i];
        adjS[i] = (v > 0.f) ? v : NEGF;
    }
    __syncthreads();
    // top-K per node row (descending, first-index tie break) + softmax weights
    if (tid < GN) {
        int j = tid;
        float* row = &adjS[j*GN];
        float nw[KNB]; int nd[KNB];
        for (int k = 0; k < KNB; k++) {
            float best = row[0]; int bi = 0;
            for (int i = 1; i < GN; i++) { float v = row[i]; if (v > best) { best = v; bi = i; } }
            row[bi] = -3.0e38f;
            bool valid = best > (NEGF * 0.5f);
            nd[k] = valid ? bi : -1;
            nw[k] = valid ? best : NEGF;
        }
        float m = nw[0];
        for (int k = 1; k < KNB; k++) m = fmaxf(m, nw[k]);
        float p[KNB], sum = 0.f;
        for (int k = 0; k < KNB; k++) { p[k] = expf(nw[k]-m); sum += p[k]; }
        float inv = 1.f / sum;
        for (int k = 0; k < KNB; k++) {
            g_softw [(b*GN+j)*KNB+k] = p[k]*inv;
            g_tknode[(b*GN+j)*KNB+k] = nd[k];
        }
    }
}

// ---------------- CX = [E(node), aggE(node)] per (b, node) + pad row ---------
// 256 threads, 4 node-rows per block
__global__ void cx_kernel(const float* __restrict__ emb)
{
    int tid = threadIdx.x;
    int row = blockIdx.x*4 + (tid>>6);
    int c = tid & 63;
    if (row >= ROWS_N) return;
    int b = row / GP1, j = row - b*GP1;
    float4* dst = (float4*)&g_CX[(size_t)row*512];
    if (j == GN) {
        float4 v = ((const float4*)emb)[c];           // embedding[0]
        dst[c] = v; dst[64+c] = v;
        return;
    }
    int item = g_ifn[b*GN+j];
    dst[c] = ((const float4*)(emb + (size_t)item*DIM))[c];
    float4 acc = {0.f,0.f,0.f,0.f};
    #pragma unroll
    for (int k = 0; k < KNB; k++) {
        float sw = g_softw[(b*GN+j)*KNB+k];
        int nd = g_tknode[(b*GN+j)*KNB+k];
        int it2 = (nd >= 0) ? g_ifn[b*GN+nd] : 0;
        float4 vv = ((const float4*)(emb + (size_t)it2*DIM))[c];
        acc.x += sw*vv.x; acc.y += sw*vv.y; acc.z += sw*vv.z; acc.w += sw*vv.w;
    }
    dst[64+c] = acc;
}

// ---------------- CH = [X(node), AGG2(node)] ---------------------------------
__global__ void ch_kernel()
{
    int tid = threadIdx.x;
    int row = blockIdx.x*4 + (tid>>6);
    int c = tid & 63;
    if (row >= ROWS_N) return;
    int b = row / GP1, j = row - b*GP1;
    float4* dst = (float4*)&g_CH[(size_t)row*512];
    const float4* xb = (const float4*)(g_Xn + (size_t)b*GP1*DIM);
    if (j == GN) {
        float4 v = xb[GN*64 + c];                     // X_pad
        dst[c] = v; dst[64+c] = v;
        return;
    }
    dst[c] = xb[j*64 + c];
    float4 acc = {0.f,0.f,0.f,0.f};
    #pragma unroll
    for (int k = 0; k < KNB; k++) {
        float sw = g_softw[(b*GN+j)*KNB+k];
        int nd = g_tknode[(b*GN+j)*KNB+k];
        int jj = (nd >= 0) ? g_canon[b*GN+nd] : GN;   // invalid -> pad row
        float4 vv = xb[jj*64 + c];
        acc.x += sw*vv.x; acc.y += sw*vv.y; acc.z += sw*vv.z; acc.w += sw*vv.w;
    }
    dst[64+c] = acc;
}

// ---------------- sb = lrelu(P[s] + Hs[b, src0|pad])  (replaces CS + big GEMM)
__global__ void sbg_kernel()
{
    int tid = threadIdx.x;
    int idx = blockIdx.x*4 + (tid>>6);                // 0..3199
    int c = tid & 63;
    int b = idx / SEQ, s = idx - b*SEQ;
    float4 p = ((const float4*)g_P)[s*64 + c];
    int src = g_src0[idx];
    int jj = (src >= 0) ? src : GN;
    float4 hv = ((const float4*)g_Hs)[(size_t)(b*GP1+jj)*64 + c];
    float4 o;
    o.x = p.x + hv.x; o.y = p.y + hv.y; o.z = p.z + hv.z; o.w = p.w + hv.w;
    o.x = o.x > 0.f ? o.x : 0.2f*o.x;
    o.y = o.y > 0.f ? o.y : 0.2f*o.y;
    o.z = o.z > 0.f ? o.z : 0.2f*o.z;
    o.w = o.w > 0.f ? o.w : 0.2f*o.w;
    ((float4*)g_sb)[(size_t)idx*64 + c] = o;
}

// ---------------- ph = path @ hidden (hidden = embedding[data]) --------------
__global__ void ph_kernel(const float* __restrict__ path,
                          const float* __restrict__ emb,
                          const int* __restrict__ data)
{
    int b = blockIdx.x;
    int n0 = blockIdx.y * 64;
    int tid = threadIdx.x;                             // 256 threads
    __shared__ float pS[SEQ*SEQ];
    __shared__ const float* rp[SEQ];
    for (int i = tid; i < SEQ*SEQ; i += 256) pS[i] = path[(size_t)b*SEQ*SEQ + i];
    if (tid < SEQ) rp[tid] = emb + (size_t)data[b*SEQ+tid]*DIM;
    __syncthreads();
    int c = tid & 63;
    int sg = tid >> 6;                                 // 0..3
    int ns = (sg < 2) ? 13 : 12;
    float acc[13];
    #pragma unroll
    for (int i = 0; i < 13; i++) acc[i] = 0.f;
    for (int t = 0; t < SEQ; t++) {
        float hv = rp[t][n0 + c];
        #pragma unroll
        for (int ss = 0; ss < 13; ss++) {
            if (ss < ns) {
                int s = sg + 4*ss;
                acc[ss] += pS[s*SEQ + t] * hv;
            }
        }
    }
    for (int ss = 0; ss < ns; ss++) {
        int s = sg + 4*ss;
        g_ph[((size_t)(b*SEQ+s))*DIM + n0 + c] = acc[ss];
    }
}

// ---------------- BM=64 GEMM (small M) ---------------------------------------
__global__ void gemm64(const float* __restrict__ A, const float* __restrict__ W,
                       float* __restrict__ C, int M, int K,
                       const float* __restrict__ bias,
                       const float* __restrict__ rowadd, int rows_per_b,
                       int do_lrelu)
{
    __shared__ __align__(16) float As[16][68];
    __shared__ __align__(16) float Ws[16][64];
    int m0 = blockIdx.x * 64;
    int n0 = blockIdx.y * 64;
    int tid = threadIdx.x;
    int tr = tid >> 4, tc = tid & 15;
    int arow = tid >> 2, acol = (tid & 3) * 4;
    int wrow = tid >> 4, wcol = (tid & 15) * 4;
    float acc[4][4] = {};
    for (int k0 = 0; k0 < K; k0 += 16) {
        float4 av = *(const float4*)&A[(size_t)(m0+arow)*K + k0 + acol];
        As[acol+0][arow] = av.x; As[acol+1][arow] = av.y;
        As[acol+2][arow] = av.z; As[acol+3][arow] = av.w;
        *(float4*)&Ws[wrow][wcol] = *(const float4*)&W[(size_t)(k0+wrow)*256 + n0 + wcol];
        __syncthreads();
        #pragma unroll
        for (int k = 0; k < 16; k++) {
            float4 a = *(const float4*)&As[k][tr*4];
            float4 w = *(const float4*)&Ws[k][tc*4];
            float ar[4] = {a.x,a.y,a.z,a.w};
            float wr[4] = {w.x,w.y,w.z,w.w};
            #pragma unroll
            for (int i = 0; i < 4; i++)
                #pragma unroll
                for (int j = 0; j < 4; j++) acc[i][j] += ar[i]*wr[j];
        }
        __syncthreads();
    }
    #pragma unroll
    for (int i = 0; i < 4; i++) {
        int r = m0 + tr*4 + i;
        int cb = n0 + tc*4;
        float4 o; float* op = &o.x;
        #pragma unroll
        for (int j = 0; j < 4; j++) {
            float v = acc[i][j];
            if (bias)   v += bias[cb+j];
            if (rowadd) v += rowadd[(r/rows_per_b)*256 + cb + j];
            if (do_lrelu) v = (v > 0.f) ? v : 0.2f*v;
            op[j] = v;
        }
        *(float4*)&C[(size_t)r*256 + cb] = o;
    }
}

// ---------------- BM=128 GEMM (large M, rows padded to multiple of 128) ------
__global__ void gemm128(const float* __restrict__ A, const float* __restrict__ W,
                        float* __restrict__ C, int K,
                        const float* __restrict__ bias,
                        const float* __restrict__ rowadd,
                        int do_lrelu)
{
    __shared__ __align__(16) float As[16][132];
    __shared__ __align__(16) float Ws[16][64];
    int m0 = blockIdx.x * 128;
    int n0 = blockIdx.y * 64;
    int tid = threadIdx.x;
    int tr = tid >> 4, tc = tid & 15;                  // 8-row x 4-col micro-tile
    int wrow = tid >> 4, wcol = (tid & 15) * 4;
    float acc[8][4] = {};
    for (int k0 = 0; k0 < K; k0 += 16) {
        #pragma unroll
        for (int t = 0; t < 2; t++) {
            int idx = tid*2 + t;
            int row = idx >> 2, cg = (idx & 3) * 4;
            float4 av = *(const float4*)&A[(size_t)(m0+row)*K + k0 + cg];
            As[cg+0][row]=av.x; As[cg+1][row]=av.y; As[cg+2][row]=av.z; As[cg+3][row]=av.w;
        }
        *(float4*)&Ws[wrow][wcol] = *(const float4*)&W[(size_t)(k0+wrow)*256 + n0 + wcol];
        __syncthreads();
        #pragma unroll
        for (int k = 0; k < 16; k++) {
            float4 a0 = *(const float4*)&As[k][tr*8];
            float4 a1 = *(const float4*)&As[k][tr*8+4];
            float4 w  = *(const float4*)&Ws[k][tc*4];
            float ar[8]={a0.x,a0.y,a0.z,a0.w,a1.x,a1.y,a1.z,a1.w};
            float wr[4]={w.x,w.y,w.z,w.w};
            #pragma unroll
            for (int i=0;i<8;i++)
                #pragma unroll
                for (int j=0;j<4;j++) acc[i][j]+=ar[i]*wr[j];
        }
        __syncthreads();
    }
    #pragma unroll
    for (int i = 0; i < 8; i++) {
        int r = m0 + tr*8 + i;
        int cb = n0 + tc*4;
        float4 o; float* op = &o.x;
        #pragma unroll
        for (int j = 0; j < 4; j++) {
            float v = acc[i][j];
            if (bias)   v += bias[cb+j];
            if (rowadd) v += rowadd[(r/SEQ)*256 + cb + j];
            if (do_lrelu) v = (v > 0.f) ? v : 0.2f*v;
            op[j] = v;
        }
        *(float4*)&C[(size_t)r*256 + cb] = o;
    }
}

// ---------------- fused: last = sum(mask)-1 ; v = h[b,last]@w_2 + b_l --------
__global__ void htv_kernel(const float* __restrict__ mask,
                           const float* __restrict__ w2,
                           const float* __restrict__ bl)
{
    int b = blockIdx.x, tid = threadIdx.x;             // 256 threads
    __shared__ float hS[256];
    __shared__ int lastS;
    if (tid == 0) {
        float s = 0.f;
        for (int i = 0; i < SEQ; i++) s += mask[b*SEQ+i];
        lastS = (int)(s - 1.0f);
    }
    __syncthreads();
    hS[tid] = g_h[((size_t)(b*SEQ+lastS))*DIM + tid];
    __syncthreads();
    float acc = bl[tid];
    for (int k = 0; k < 256; k++) acc += hS[k]*w2[k*256 + tid];
    g_v[b*256 + tid] = acc;
}

// ---------------- vec-mat: y[b] = (x[b] @ Wm) (+bias) (lrelu?) ---------------
__global__ void vecmat(const float* __restrict__ x, int xstride,
                       const float* __restrict__ Wm, int K,
                       const float* __restrict__ bias,
                       float* __restrict__ y, int do_lrelu)
{
    int b = blockIdx.x, tid = threadIdx.x;             // 256 threads
    __shared__ float xS[512];
    for (int i = tid; i < K; i += 256) xS[i] = x[(size_t)b*xstride + i];
    __syncthreads();
    float acc = bias ? bias[tid] : 0.f;
    for (int k = 0; k < K; k++) acc += xS[k]*Wm[(size_t)k*256 + tid];
    if (do_lrelu) acc = (acc > 0.f) ? acc : 0.2f*acc;
    y[b*256 + tid] = acc;
}

// ---------------- softmax pooling: e=z.q ; softmax ; out = sum p*h -----------
__global__ void pool_kernel(const float* __restrict__ z, const float* __restrict__ qv,
                            const float* __restrict__ hsrc,
                            const float* __restrict__ mask,   // nullable
                            float* __restrict__ outv,         // used if CO==null
                            const float* __restrict__ slin,   // used if CO!=null
                            float* __restrict__ CO)           // nullable
{
    int b = blockIdx.x, tid = threadIdx.x;
    int lane = tid & 31, wp = tid >> 5;
    __shared__ float eS[SEQ], pS[SEQ];
    for (int s = wp; s < SEQ; s += 8) {
        const float* zr = z + ((size_t)(b*SEQ+s))*DIM;
        float d = 0.f;
        for (int i = lane; i < DIM; i += 32) d += zr[i]*qv[i];
        for (int o = 16; o; o >>= 1) d += __shfl_xor_sync(0xffffffffu, d, o);
        if (!lane) eS[s] = d;
    }
    __syncthreads();
    if (tid == 0) {
        float m = -3.4e38f;
        for (int s = 0; s < SEQ; s++) {
            float e = eS[s];
            if (mask && !(mask[b*SEQ+s] > 0.f)) e = NEGF;
            eS[s] = e; m = fmaxf(m, e);
        }
        float sum = 0.f;
        for (int s = 0; s < SEQ; s++) { float p = expf(eS[s]-m); pS[s] = p; sum += p; }
        float inv = 1.f / sum;
        for (int s = 0; s < SEQ; s++) pS[s] *= inv;
    }
    __syncthreads();
    float acc = 0.f;
    for (int s = 0; s < SEQ; s++) acc += pS[s] * hsrc[((size_t)(b*SEQ+s))*DIM + tid];
    if (CO) {
        CO[b*512 + tid]       = slin[b*256 + tid];
        CO[b*512 + 256 + tid] = acc;
    } else {
        outv[b*256 + tid] = acc;
    }
}

// ---------------- launch ----------------------------------------------------
extern "C" void kernel_launch(void* const* d_in, const int* in_sizes, int n_in,
                              void* d_out, int out_size)
{
    const int*   data  = (const int*)  d_in[0];
    const float* mask  = (const float*)d_in[1];
    const float* adj   = (const float*)d_in[2];
    const int*   alias = (const int*)  d_in[3];
    const int*   cur   = (const int*)  d_in[4];
    const float* path  = (const float*)d_in[5];
    const float* emb   = (const float*)d_in[6];
    const float* pos   = (const float*)d_in[7];
    const float* w3    = (const float*)d_in[8];
    const float* b1    = (const float*)d_in[9];
    const float* q     = (const float*)d_in[10];
    const float* wg1   = (const float*)d_in[11];
    const float* wg2   = (const float*)d_in[12];
    const float* b2    = (const float*)d_in[13];
    const float* wh    = (const float*)d_in[14];
    const float* wp    = (const float*)d_in[15];
    const float* w1    = (const float*)d_in[16];
    const float* w2    = (const float*)d_in[17];
    const float* bl    = (const float*)d_in[18];
    const float* ql    = (const float*)d_in[19];
    const float* wagg  = (const float*)d_in[20];   // [2,512,256]
    const float* bagg  = (const float*)d_in[21];   // [2,256]
    float* out = (float*)d_out;

    float *CX,*Xn,*CH,*Hn,*Hs,*P,*ph,*h,*v,*z,*sl,*sb,*vg,*zg,*CO;
    cudaGetSymbolAddress((void**)&CX, g_CX);
    cudaGetSymbolAddress((void**)&Xn, g_Xn);
    cudaGetSymbolAddress((void**)&CH, g_CH);
    cudaGetSymbolAddress((void**)&Hn, g_Hn);
    cudaGetSymbolAddress((void**)&Hs, g_Hs);
    cudaGetSymbolAddress((void**)&P,  g_P);
    cudaGetSymbolAddress((void**)&ph, g_ph);
    cudaGetSymbolAddress((void**)&h,  g_h);
    cudaGetSymbolAddress((void**)&v,  g_v);
    cudaGetSymbolAddress((void**)&z,  g_z);
    cudaGetSymbolAddress((void**)&sl, g_sl);
    cudaGetSymbolAddress((void**)&sb, g_sb);
    cudaGetSymbolAddress((void**)&vg, g_vg);
    cudaGetSymbolAddress((void**)&zg, g_zg);
    cudaGetSymbolAddress((void**)&CO, g_CO);

    // Side stream + fork/join events (created once, outside any capture; every
    // call performs the identical launch sequence).
    static cudaStream_t sB = nullptr;
    static cudaEvent_t evF = nullptr, evJ = nullptr;
    if (!sB) {
        cudaStreamCreateWithFlags(&sB, cudaStreamNonBlocking);
        cudaEventCreateWithFlags(&evF, cudaEventDisableTiming);
        cudaEventCreateWithFlags(&evJ, cudaEventDisableTiming);
    }

    // ---- fork: local-intent chain runs on sB concurrently with global chain ----
    cudaEventRecord(evF, 0);
    cudaStreamWaitEvent(sB, evF, 0);

    // ==== stream 0: GlobalIntent chain ====
    setup_kernel<<<BATCH, 64>>>(data, adj, alias, cur);
    cx_kernel<<<(ROWS_N+3)/4, 256>>>(emb);
    // X = lrelu(CX @ w_agg0 + b_agg0)   [3328,512]x[512,256]
    gemm128<<<dim3(ROWS_PAD/128,4), 256>>>(CX, wagg, Xn, 512, bagg, nullptr, 1);
    ch_kernel<<<(ROWS_N+3)/4, 256>>>();
    // H = lrelu(CH @ w_agg1 + b_agg1)
    gemm128<<<dim3(ROWS_PAD/128,4), 256>>>(CH, wagg + 512*256, Hn, 512, bagg + 256, nullptr, 1);
    // Hs = Hn @ w3_bottom   (h_global half of the fusion GEMM, per node row)
    gemm128<<<dim3(ROWS_PAD/128,4), 256>>>(Hn, w3 + 256*256, Hs, 256, nullptr, nullptr, 0);

    // ==== stream sB: LocalIntent chain (independent of global chain) ====
    // P = pos[:64] @ w3_top + b1   (batch-independent half of fusion GEMM)
    gemm64<<<dim3(1,4), 256, 0, sB>>>(pos, w3, P, 64, 256, b1, nullptr, 1, 0);
    ph_kernel<<<dim3(BATCH,4), 256, 0, sB>>>(path, emb, data);
    gemm128<<<dim3(25,4), 256, 0, sB>>>(ph, wp, h, 256, nullptr, nullptr, 1);   // h = lrelu(ph@w_p)
    htv_kernel<<<BATCH, 256, 0, sB>>>(mask, w2, bl);                            // v = h[last]@w_2+b_l
    gemm128<<<dim3(25,4), 256, 0, sB>>>(h, w1, z, 256, nullptr, v, 1);          // z = lrelu(h@w_1+v[b])
    pool_kernel<<<BATCH, 256, 0, sB>>>(z, ql, h, mask, sl, nullptr, nullptr);   // s_l
    vecmat<<<BATCH, 256, 0, sB>>>(sl, 256, wg2, 256, b2, vg, 0);                // vg = s_l@w_g2+b_2
    cudaEventRecord(evJ, sB);

    // ---- join ----
    cudaStreamWaitEvent(0, evJ, 0);

    // ==== stream 0: fusion tail ====
    sbg_kernel<<<BATCH*SEQ/4, 256>>>();                                         // s = lrelu(P+Hs+b1)
    gemm128<<<dim3(25,4), 256>>>(sb, wg1, zg, 256, nullptr, vg, 1);             // zg
    pool_kernel<<<BATCH, 256>>>(zg, q, sb, nullptr, nullptr, sl, CO);           // s_g, CO=[s_l,s_g]
    vecmat<<<BATCH, 256>>>(CO, 512, wh, 512, nullptr, out, 1);                  // out = lrelu(CO@w_h)
}